// round 16
// baseline (speedup 1.0000x reference)
#include <cuda_runtime.h>
#include <cstdint>

#define CIN 3
#define COUT 16
#define HH 32
#define WW 32
#define OH 30
#define OW 30

typedef unsigned long long u64;

// ---- f32x2 packed-math helpers (SASS FFMA2 via PTX only) ----
__device__ __forceinline__ u64 pk2(float a, float b) {
    u64 r; asm("mov.b64 %0, {%1, %2};" : "=l"(r) : "f"(a), "f"(b)); return r;
}
__device__ __forceinline__ u64 dup2(float a) {
    u64 r; asm("mov.b64 %0, {%1, %1};" : "=l"(r) : "f"(a)); return r;
}
__device__ __forceinline__ u64 fma2(u64 a, u64 b, u64 c) {
    u64 d; asm("fma.rn.f32x2 %0, %1, %2, %3;" : "=l"(d) : "l"(a), "l"(b), "l"(c)); return d;
}
__device__ __forceinline__ void upk2(u64 v, float& a, float& b) {
    asm("mov.b64 {%0, %1}, %2;" : "=f"(a), "=f"(b) : "l"(v));
}
// activation tail: relu(v)*min(v+3,6)/6 == max(v,0)*min(t,1), t = v/6+0.5
__device__ __forceinline__ float hswish_relu(float v, float t) {
    return fmaxf(v, 0.0f) * fminf(t, 1.0f);
}

// Direct conv v9 — column-pair packing with a SHIFTED smem shadow copy.
// Grid 8192: block b -> image b>>1, channel-half b&1. 128 threads = 4 warps.
// Warp w -> channel pair; lane L -> channel c0+(L>>4), column pair k=L&15
// (acc f32x2 = {out[2k], out[2k+1]} of ONE channel; k==15 idle).
// smem holds the image TWICE: s1[p] = x[p], s2[p] = x[p+1]. All three tap
// operands {x2k,x2k+1} / {x2k+1,x2k+2} / {x2k+2,x2k+3} are then ALIGNED
// LDS.64 (s1@2k, s2@2k, s1@2k+2) — zero dup/pack/unpack MOVs in the hot loop
// (R12's alu=38% and R15's 9 dup2/row both eliminated). Half-warps read the
// same addresses -> smem broadcast, 1 wavefront per LDS.64.
// Weights {w,w} duplicated per lane once at setup. One STG.64 per lane-row.
__global__ void __launch_bounds__(128, 4) conv3x3_hswish_kernel(
    const float* __restrict__ x,
    const float* __restrict__ wgt,
    const float* __restrict__ bias,
    float* __restrict__ out)
{
    __shared__ __align__(16) float s1[CIN * HH * WW];       // image
    __shared__ __align__(16) float s2[CIN * HH * WW];       // image shifted by 1

    const int n    = blockIdx.x >> 1;
    const int half = blockIdx.x & 1;
    const int tid  = threadIdx.x;

    {   // coalesced image load + shifted shadow copy
        const float4* src = reinterpret_cast<const float4*>(x + (size_t)n * (CIN * HH * WW));
        float4* dst = reinterpret_cast<float4*>(s1);
        #pragma unroll
        for (int i = 0; i < 6; i++) {
            const int idx = tid + i * 128;
            const float4 f = src[idx];
            dst[idx] = f;
            const int p = idx * 4;          // s2[p-1..p+2] = {f.x, f.y, f.z, f.w}
            if (p) s2[p - 1] = f.x;
            s2[p + 0] = f.y;
            s2[p + 1] = f.z;
            s2[p + 2] = f.w;
        }
    }
    __syncthreads();

    const int warp = tid >> 5;
    const int lane = tid & 31;
    const int c0   = (half * 4 + warp) * 2;
    const int ch   = c0 + (lane >> 4);       // this lane's channel
    const int kk   = lane & 15;              // column pair (0..14 active)

    // per-lane duplicated weights {w,w} and bias
    u64 wd[27];
    #pragma unroll
    for (int t = 0; t < 27; t++) wd[t] = dup2(wgt[ch * 27 + t]);
    const u64 bd    = dup2(bias[ch]);
    const u64 sixth = dup2(1.0f / 6.0f);
    const u64 halfc = dup2(0.5f);

    if (kk == 15) return;   // lanes 15/31 idle; barrier already done

    const float* b1 = s1 + 2 * kk;           // {x[2k+..], ...}
    const float* b2 = s2 + 2 * kk;           // shifted: {x[2k+1+..], ...}
    float* outp = out + ((size_t)n * COUT + ch) * (OH * OW) + 2 * kk;

    // double-buffered row window: per ci {q01, qm, q23}; parity compile-time.
    u64 qa[9], qb[9];
    u64 acc[3];             // acc[y % 3] = {out[y][2k], out[y][2k+1]}

    #pragma unroll
    for (int ci = 0; ci < CIN; ci++) {       // preload input row 0
        qa[ci * 3 + 0] = *reinterpret_cast<const u64*>(b1 + ci * 1024 + 0);
        qa[ci * 3 + 1] = *reinterpret_cast<const u64*>(b2 + ci * 1024 + 0);
        qa[ci * 3 + 2] = *reinterpret_cast<const u64*>(b1 + ci * 1024 + 2);
    }

    #pragma unroll
    for (int r = 0; r < 32; r++) {
        // prefetch input row r+1 into the other buffer (full-row distance)
        if (r < 31) {
            #pragma unroll
            for (int ci = 0; ci < CIN; ci++) {
                const int off = ci * 1024 + (r + 1) * 32;
                const u64 v0 = *reinterpret_cast<const u64*>(b1 + off);
                const u64 v1 = *reinterpret_cast<const u64*>(b2 + off);
                const u64 v2 = *reinterpret_cast<const u64*>(b1 + off + 2);
                if (r & 1) { qa[ci * 3 + 0] = v0; qa[ci * 3 + 1] = v1; qa[ci * 3 + 2] = v2; }
                else       { qb[ci * 3 + 0] = v0; qb[ci * 3 + 1] = v1; qb[ci * 3 + 2] = v2; }
            }
        }

        #pragma unroll
        for (int t = 0; t < 9; t++) {
            const int ci = t / 3, kx = t % 3;
            const u64 q = (r & 1) ? qb[t] : qa[t];   // tap operand, no MOVs
            if (r >= 2)
                acc[(r - 2) % 3] = fma2(q, wd[ci * 9 + 6 + kx], acc[(r - 2) % 3]);
            if (r >= 1 && r <= 30)
                acc[(r - 1) % 3] = fma2(q, wd[ci * 9 + 3 + kx], acc[(r - 1) % 3]);
            if (r <= 29) {
                // bias folded into the first tap of each output row
                acc[r % 3] = (t == 0) ? fma2(q, wd[0], bd)
                                      : fma2(q, wd[ci * 9 + 0 + kx], acc[r % 3]);
            }
        }

        // output row y = r-2 complete: packed t, scalar tail, one STG.64
        if (r >= 2) {
            const u64 v = acc[(r - 2) % 3];
            const u64 t = fma2(v, sixth, halfc);       // {v0,v1}/6 + 0.5
            float v0, v1, t0, t1;
            upk2(v, v0, v1);
            upk2(t, t0, t1);
            float2 st;
            st.x = hswish_relu(v0, t0);
            st.y = hswish_relu(v1, t1);
            *reinterpret_cast<float2*>(outp + (r - 2) * OW) = st;
        }
    }
}

extern "C" void kernel_launch(void* const* d_in, const int* in_sizes, int n_in,
                              void* d_out, int out_size) {
    const float* x = (const float*)d_in[0];
    const float* w = (const float*)d_in[1];
    const float* b = (const float*)d_in[2];
    float* out = (float*)d_out;

    const int N = in_sizes[0] / (CIN * HH * WW);   // 4096
    conv3x3_hswish_kernel<<<N * 2, 128>>>(x, w, b, out);
}

// round 17
// speedup vs baseline: 1.1280x; 1.1280x over previous
#include <cuda_runtime.h>
#include <cstdint>

#define CIN 3
#define COUT 16
#define HH 32
#define WW 32
#define OH 30
#define OW 30

typedef unsigned long long u64;

// ---- f32x2 packed-math helpers (SASS FFMA2 via PTX only) ----
__device__ __forceinline__ u64 pk2(float a, float b) {
    u64 r; asm("mov.b64 %0, {%1, %2};" : "=l"(r) : "f"(a), "f"(b)); return r;
}
__device__ __forceinline__ u64 dup2(float a) {
    u64 r; asm("mov.b64 %0, {%1, %1};" : "=l"(r) : "f"(a)); return r;
}
__device__ __forceinline__ u64 fma2(u64 a, u64 b, u64 c) {
    u64 d; asm("fma.rn.f32x2 %0, %1, %2, %3;" : "=l"(d) : "l"(a), "l"(b), "l"(c)); return d;
}
__device__ __forceinline__ void upk2(u64 v, float& a, float& b) {
    asm("mov.b64 {%0, %1}, %2;" : "=f"(a), "=f"(b) : "l"(v));
}
// activation: relu(v)*min(v+3,6)/6 == max(v,0)*min(v/6+0.5, 1)
// fmaf with immediates -> FFMA-imm (rt=1), no constant registers needed.
__device__ __forceinline__ float hswish_relu(float v) {
    return fmaxf(v, 0.0f) * fminf(fmaf(v, 1.0f / 6.0f, 0.5f), 1.0f);
}

// Direct conv v10 = R15 (80.3us, 96 regs, occ 5) on a register diet for
// SIX blocks/SM (24 warps; cap 85 regs): single prefetch buffer (-9 regs,
// loads for row r+1 emitted after row r's last reads — ptxas schedules them
// ~40 slots ahead of use in the unrolled stream, > 29cyc LDS latency) and
// scalar-immediate epilogue (-4 const regs; FFMA-imm is rt=1).
// Structure otherwise identical: grid 8192 (image, channel-half); 128 thr =
// 4 warps; warp -> channel pair; lane = output column (30 active); scalar
// LDS.32 (crossbar-safe: R4/R16 proved any LDS.64 operand scheme saturates
// the crossbar at 2 wavefronts/load) + one dup2 per value feeding 3 FFMA2.
__global__ void __launch_bounds__(128, 6) conv3x3_hswish_kernel(
    const float* __restrict__ x,
    const float* __restrict__ wgt,
    const float* __restrict__ bias,
    float* __restrict__ out)
{
    __shared__ float s_in[CIN * HH * WW];   // 12 KB

    const int n    = blockIdx.x >> 1;
    const int half = blockIdx.x & 1;
    const int tid  = threadIdx.x;

    {   // coalesced image load: 768 float4 / 128 threads = 6 each
        const float4* src = reinterpret_cast<const float4*>(x + (size_t)n * (CIN * HH * WW));
        float4* dst = reinterpret_cast<float4*>(s_in);
        #pragma unroll
        for (int i = 0; i < 6; i++) dst[tid + i * 128] = src[tid + i * 128];
    }
    __syncthreads();

    const int warp = tid >> 5;
    const int lane = tid & 31;
    const int c0   = (half * 4 + warp) * 2;   // channel pair

    // packed weights: wp[ci*9 + ky*3 + kx] = {w[c0], w[c0+1]}
    u64 wp[27];
    #pragma unroll
    for (int t = 0; t < 27; t++)
        wp[t] = pk2(wgt[c0 * 27 + t], wgt[(c0 + 1) * 27 + t]);
    const u64 bp = pk2(bias[c0], bias[c0 + 1]);

    if (lane >= OW) return;   // barrier done; lanes 30/31 retire

    const float* base = s_in + lane;   // [ci*1024 + row*32 + kx]
    float* out0 = out + ((size_t)n * COUT + c0) * (OH * OW) + lane;

    // single row buffer; next-row loads are emitted after this row's reads.
    float nb[9];
    u64 acc[3];               // acc[y % 3] = accumulator for output row y

    #pragma unroll
    for (int ci = 0; ci < CIN; ci++)
        #pragma unroll
        for (int kx = 0; kx < 3; kx++)
            nb[ci * 3 + kx] = base[ci * 1024 + kx];   // input row 0

    #pragma unroll
    for (int r = 0; r < 32; r++) {
        #pragma unroll
        for (int t = 0; t < 9; t++) {
            const int ci = t / 3, kx = t % 3;
            const u64 dv = dup2(nb[t]);               // one dup, 3 uses
            if (r >= 2)
                acc[(r - 2) % 3] = fma2(dv, wp[ci * 9 + 6 + kx], acc[(r - 2) % 3]);
            if (r >= 1 && r <= 30)
                acc[(r - 1) % 3] = fma2(dv, wp[ci * 9 + 3 + kx], acc[(r - 1) % 3]);
            if (r <= 29) {
                // bias folded into the first tap of each output row
                acc[r % 3] = (t == 0) ? fma2(dv, wp[0], bp)
                                      : fma2(dv, wp[ci * 9 + 0 + kx], acc[r % 3]);
            }
        }

        // load input row r+1 (scheduled early by ptxas as deps allow)
        if (r < 31) {
            #pragma unroll
            for (int ci = 0; ci < CIN; ci++)
                #pragma unroll
                for (int kx = 0; kx < 3; kx++)
                    nb[ci * 3 + kx] = base[ci * 1024 + (r + 1) * 32 + kx];
        }

        // output row y = r-2 complete
        if (r >= 2) {
            float v0, v1;
            upk2(acc[(r - 2) % 3], v0, v1);
            const int yoff = (r - 2) * OW;
            out0[yoff]           = hswish_relu(v0);
            out0[OH * OW + yoff] = hswish_relu(v1);
        }
    }
}

extern "C" void kernel_launch(void* const* d_in, const int* in_sizes, int n_in,
                              void* d_out, int out_size) {
    const float* x = (const float*)d_in[0];
    const float* w = (const float*)d_in[1];
    const float* b = (const float*)d_in[2];
    float* out = (float*)d_out;

    const int N = in_sizes[0] / (CIN * HH * WW);   // 4096
    conv3x3_hswish_kernel<<<N * 2, 128>>>(x, w, b, out);
}